// round 1
// baseline (speedup 1.0000x reference)
#include <cuda_runtime.h>
#include <math.h>

#define Bsz 8192
#define Gd  1024
#define Ed  256
#define Kd  2048
#define PNULL 0.1f

// ---- scratch (no allocs allowed; __device__ globals are the sanctioned path) ----
__device__ float g_pik[(size_t)Bsz * Kd];   // 64 MB: pik (logits pre-softmax, then pik)
__device__ float g_w  [(size_t)Bsz * Kd];   // 64 MB: w / u scratch
__device__ float g_z  [(size_t)Bsz * Ed];   // 8 MB
__device__ float g_c2a[Kd];
__device__ float g_c2b[Kd];
__device__ float g_rows[Bsz];               // 1/sum(w) or 1/(0.1+sum(u))
__device__ float g_z2 [Bsz];

// ---- column squared-means ----
__global__ void k_c2(const float* __restrict__ xa, const float* __restrict__ xb) {
    int k = blockIdx.x * blockDim.x + threadIdx.x;
    if (k >= Kd) return;
    float s = 0.f;
    for (int g = 0; g < Gd; g++) { float v = xa[(size_t)g * Kd + k]; s += v * v; }
    g_c2a[k] = s / Gd;
    float t = 0.f;
    for (int e = 0; e < Ed; e++) { float v = xb[(size_t)e * Kd + k]; t += v * v; }
    g_c2b[k] = t / Ed;
}

// ---- generic 128x128x8 SGEMM with fused epilogues ----
// epi: 0 -> out = acc*alpha - c2vec[n]                      (logits)
//      1 -> out = acc*alpha * (rowvec ? rowvec[m] : 1)      (z update)
//      2 -> out = pik[idx] * expf(acc*alpha - c2vec[n])     (w)
//      3 -> out = expf(acc*alpha - c2vec[n] - rowvec[m])    (u)
//      4 -> loss: d = acc - images[m,n]; atomically accumulate mean d^2 per row
template <bool TRANSB>
__global__ void __launch_bounds__(256, 2)
gemm128(const float* __restrict__ A, const float* __restrict__ Bm,
        int Kin, int lda, int ldb, int ldc,
        float alpha, int epi,
        float* __restrict__ out,
        const float* __restrict__ pik,
        const float* __restrict__ c2vec,
        const float* __restrict__ rowvec,
        const float* __restrict__ arowscale,
        const float* __restrict__ images,
        float* __restrict__ lossout)
{
    __shared__ float As[8][128];
    __shared__ float Bs[8][128];
    __shared__ float rowacc[128];

    const int tid = threadIdx.x;
    const int m0 = blockIdx.y * 128, n0 = blockIdx.x * 128;

    const int a_row = tid >> 1;
    const int a_k4  = (tid & 1) * 4;
    const float ascale = arowscale ? arowscale[m0 + a_row] : 1.0f;
    const float* Aptr = A + (size_t)(m0 + a_row) * lda + a_k4;

    const int tx = tid & 15, ty = tid >> 4;

    float acc[8][8];
#pragma unroll
    for (int i = 0; i < 8; i++)
#pragma unroll
        for (int j = 0; j < 8; j++) acc[i][j] = 0.f;

    for (int kk = 0; kk < Kin; kk += 8) {
        float4 av = *(const float4*)(Aptr + kk);
        As[a_k4 + 0][a_row] = av.x * ascale;
        As[a_k4 + 1][a_row] = av.y * ascale;
        As[a_k4 + 2][a_row] = av.z * ascale;
        As[a_k4 + 3][a_row] = av.w * ascale;

        if (!TRANSB) {
            int b_k = tid >> 5, b_n = (tid & 31) * 4;
            float4 bv = *(const float4*)(Bm + (size_t)(kk + b_k) * ldb + n0 + b_n);
            *(float4*)&Bs[b_k][b_n] = bv;
        } else {
            int bt_n = tid >> 1, bt_k4 = (tid & 1) * 4;
            float4 bv = *(const float4*)(Bm + (size_t)(n0 + bt_n) * ldb + kk + bt_k4);
            Bs[bt_k4 + 0][bt_n] = bv.x;
            Bs[bt_k4 + 1][bt_n] = bv.y;
            Bs[bt_k4 + 2][bt_n] = bv.z;
            Bs[bt_k4 + 3][bt_n] = bv.w;
        }
        __syncthreads();

#pragma unroll
        for (int k = 0; k < 8; k++) {
            float a[8], b[8];
#pragma unroll
            for (int i = 0; i < 8; i++) a[i] = As[k][ty * 8 + i];
#pragma unroll
            for (int j = 0; j < 8; j++) b[j] = Bs[k][tx * 8 + j];
#pragma unroll
            for (int i = 0; i < 8; i++)
#pragma unroll
                for (int j = 0; j < 8; j++) acc[i][j] += a[i] * b[j];
        }
        __syncthreads();
    }

    const int mb = m0 + ty * 8, nb = n0 + tx * 8;

    if (epi == 4) {
        if (tid < 128) rowacc[tid] = 0.f;
        __syncthreads();
#pragma unroll
        for (int i = 0; i < 8; i++) {
            float s = 0.f;
#pragma unroll
            for (int j = 0; j < 8; j++) {
                float d = acc[i][j] - images[(size_t)(mb + i) * Gd + nb + j];
                s += d * d;
            }
            atomicAdd(&rowacc[ty * 8 + i], s);
        }
        __syncthreads();
        if (tid < 128) atomicAdd(&lossout[m0 + tid], rowacc[tid] * (1.0f / Gd));
    } else {
#pragma unroll
        for (int i = 0; i < 8; i++) {
#pragma unroll
            for (int j = 0; j < 8; j++) {
                int m = mb + i, n = nb + j;
                size_t idx = (size_t)m * ldc + n;
                float v = acc[i][j] * alpha;
                float o;
                if (epi == 0)      o = v - c2vec[n];
                else if (epi == 1) o = rowvec ? v * rowvec[m] : v;
                else if (epi == 2) o = pik[idx] * expf(v - c2vec[n]);
                else               o = expf(v - c2vec[n] - rowvec[m]);
                out[idx] = o;
            }
        }
    }
}

// ---- row softmax over K=2048, in place ----
__global__ void k_softmax(float* __restrict__ p) {
    __shared__ float red[256];
    const int b = blockIdx.x;
    float* row = p + (size_t)b * Kd;
    const int t = threadIdx.x;
    float vals[8];
    float lmax = -1e30f;
#pragma unroll
    for (int i = 0; i < 8; i++) { vals[i] = row[t + i * 256]; lmax = fmaxf(lmax, vals[i]); }
    red[t] = lmax; __syncthreads();
    for (int s = 128; s > 0; s >>= 1) { if (t < s) red[t] = fmaxf(red[t], red[t + s]); __syncthreads(); }
    float m = red[0]; __syncthreads();
    float lsum = 0.f;
#pragma unroll
    for (int i = 0; i < 8; i++) { vals[i] = expf(vals[i] - m); lsum += vals[i]; }
    red[t] = lsum; __syncthreads();
    for (int s = 128; s > 0; s >>= 1) { if (t < s) red[t] += red[t + s]; __syncthreads(); }
    float inv = 1.0f / red[0];
#pragma unroll
    for (int i = 0; i < 8; i++) row[t + i * 256] = vals[i] * inv;
}

// ---- row sum of a (B,K) buffer; mode 0: store 1/sum, mode 1: store 1/(PNULL+sum) ----
__global__ void k_rowsum(const float* __restrict__ w, int mode) {
    __shared__ float red[256];
    const int b = blockIdx.x;
    const float* row = w + (size_t)b * Kd;
    const int t = threadIdx.x;
    float s = 0.f;
#pragma unroll
    for (int i = 0; i < 8; i++) s += row[t + i * 256];
    red[t] = s; __syncthreads();
    for (int st = 128; st > 0; st >>= 1) { if (t < st) red[t] += red[t + st]; __syncthreads(); }
    if (t == 0) g_rows[b] = (mode == 0) ? 1.0f / red[0] : 1.0f / (PNULL + red[0]);
}

// ---- z2[b] = mean_e z^2 ----
__global__ void k_z2(void) {
    __shared__ float red[256];
    const int b = blockIdx.x;
    const int t = threadIdx.x;
    float v = g_z[(size_t)b * Ed + t];
    red[t] = v * v; __syncthreads();
    for (int st = 128; st > 0; st >>= 1) { if (t < st) red[t] += red[t + st]; __syncthreads(); }
    if (t == 0) g_z2[b] = red[0] / Ed;
}

extern "C" void kernel_launch(void* const* d_in, const int* in_sizes, int n_in,
                              void* d_out, int out_size) {
    (void)in_sizes; (void)n_in; (void)out_size;
    const float* images = (const float*)d_in[0];
    const float* xa     = (const float*)d_in[1];
    const float* xb     = (const float*)d_in[2];
    float* loss = (float*)d_out;

    float *pik, *wbuf, *zbuf, *c2a, *c2b, *rows, *z2;
    cudaGetSymbolAddress((void**)&pik,  g_pik);
    cudaGetSymbolAddress((void**)&wbuf, g_w);
    cudaGetSymbolAddress((void**)&zbuf, g_z);
    cudaGetSymbolAddress((void**)&c2a,  g_c2a);
    cudaGetSymbolAddress((void**)&c2b,  g_c2b);
    cudaGetSymbolAddress((void**)&rows, g_rows);
    cudaGetSymbolAddress((void**)&z2,   g_z2);

    dim3 blk(256);
    dim3 gridBK(Kd / 128, Bsz / 128);  // (16,64)
    dim3 gridBE(Ed / 128, Bsz / 128);  // (2,64)
    dim3 gridBG(Gd / 128, Bsz / 128);  // (8,64)

    // column squared-means
    k_c2<<<Kd / 256, blk>>>(xa, xb);

    // logits = images@xa * (2/G) - c2a   (x^2 row term drops out of softmax)
    gemm128<false><<<gridBK, blk>>>(images, xa, Gd, Gd, Kd, Kd, 2.0f / Gd, 0,
                                    pik, nullptr, c2a, nullptr, nullptr, nullptr, nullptr);
    // pik = softmax(logits)
    k_softmax<<<Bsz, blk>>>(pik);

    // z = pik @ xb^T
    gemm128<true><<<gridBE, blk>>>(pik, xb, Kd, Kd, Kd, Ed, 1.0f, 1,
                                   zbuf, nullptr, nullptr, nullptr, nullptr, nullptr, nullptr);

    // 4 EM steps (P_NULL and exp(-z2) row constants cancel in xp = w/sum(w))
    for (int s = 0; s < 4; s++) {
        // w = pik * exp((z@xb)*2/E - c2b)
        gemm128<false><<<gridBK, blk>>>(zbuf, xb, Ed, Ed, Kd, Kd, 2.0f / Ed, 2,
                                        wbuf, pik, c2b, nullptr, nullptr, nullptr, nullptr);
        k_rowsum<<<Bsz, blk>>>(wbuf, 0);
        // z = (w @ xb^T) / sum(w)
        gemm128<true><<<gridBE, blk>>>(wbuf, xb, Kd, Kd, Kd, Ed, 1.0f, 1,
                                       zbuf, nullptr, nullptr, rows, nullptr, nullptr, nullptr);
    }

    // decode: u = exp((z@xb)*2/E - z2 - c2b)
    k_z2<<<Bsz, blk>>>();
    gemm128<false><<<gridBK, blk>>>(zbuf, xb, Ed, Ed, Kd, Kd, 2.0f / Ed, 3,
                                    wbuf, nullptr, c2b, z2, nullptr, nullptr, nullptr);
    k_rowsum<<<Bsz, blk>>>(wbuf, 1);  // rows = 1/(0.1 + sum(u))

    // loss[b] = mean_g ((u*rows)@xa^T - images)^2, fused (recon never materialized)
    cudaMemsetAsync(loss, 0, Bsz * sizeof(float));
    gemm128<true><<<gridBG, blk>>>(wbuf, xa, Kd, Kd, Kd, Gd, 1.0f, 4,
                                   nullptr, nullptr, nullptr, nullptr, rows, images, loss);
}

// round 3
// speedup vs baseline: 6.4768x; 6.4768x over previous
#include <cuda_runtime.h>
#include <cuda_bf16.h>
#include <math.h>
#include <stdint.h>

#define Bsz 8192
#define Gd  1024
#define Ed  256
#define Kd  2048
#define PNULL 0.1f

// ---------------- scratch (device globals; no allocs allowed) ----------------
__device__ float          g_logits[(size_t)Bsz * Kd];   // 64 MB
__device__ __nv_bfloat16  g_pik  [(size_t)Bsz * Kd];    // 32 MB
__device__ __nv_bfloat16  g_w    [(size_t)Bsz * Kd];    // 32 MB
__device__ __nv_bfloat16  g_z    [(size_t)Bsz * Ed];    // 4 MB
__device__ __nv_bfloat16  g_imgs [(size_t)Bsz * Gd];    // 16 MB
__device__ __nv_bfloat16  g_xa   [(size_t)Gd * Kd];     // (G,K)
__device__ __nv_bfloat16  g_xaT  [(size_t)Kd * Gd];     // (K,G)
__device__ __nv_bfloat16  g_xb   [(size_t)Ed * Kd];     // (E,K)
__device__ __nv_bfloat16  g_xbT  [(size_t)Kd * Ed];     // (K,E)
__device__ float g_c2a[Kd], g_c2b[Kd], g_rows[Bsz], g_z2[Bsz];

// ---------------- helpers ----------------
__device__ __forceinline__ uint32_t s2u(const void* p) {
    uint32_t a;
    asm("{ .reg .u64 t; cvta.to.shared.u64 t, %1; cvt.u32.u64 %0, t; }" : "=r"(a) : "l"(p));
    return a;
}
#define SWZ(o) ((o) ^ (((o) >> 3) & 0x70))

__device__ __forceinline__ void cp16(uint32_t dst, const void* src) {
    asm volatile("cp.async.cg.shared.global [%0], [%1], 16;" :: "r"(dst), "l"(src));
}
#define CP_COMMIT()   asm volatile("cp.async.commit_group;" ::: "memory")
#define CP_WAIT(n)    asm volatile("cp.async.wait_group %0;" :: "n"(n) : "memory")

#define LDSM4(r, addr)                                                              \
    asm volatile("ldmatrix.sync.aligned.m8n8.x4.shared.b16 {%0,%1,%2,%3}, [%4];"    \
        : "=r"((r)[0]), "=r"((r)[1]), "=r"((r)[2]), "=r"((r)[3]) : "r"(addr))

#define MMA(d, a, b0, b1)                                                           \
    asm volatile("mma.sync.aligned.m16n8k16.row.col.f32.bf16.bf16.f32 "             \
        "{%0,%1,%2,%3}, {%4,%5,%6,%7}, {%8,%9}, {%0,%1,%2,%3};"                     \
        : "+f"((d)[0]), "+f"((d)[1]), "+f"((d)[2]), "+f"((d)[3])                    \
        : "r"((a)[0]), "r"((a)[1]), "r"((a)[2]), "r"((a)[3]), "r"(b0), "r"(b1))

// ---------------- mma.sync GEMM: D[128 x 128] tile = A(MxK,K-major) . B(NxK,K-major)^T
// EPI 0: out_f32 = acc*alpha - c2[n]                      (logits)
//     1: out_bf16 = acc * (rowvec ? rowvec[m] : 1)        (z)
//     2: out_bf16 = pik[m,n] * exp(acc*alpha - c2[n])     (w)  [pik ld is Kd wide]
//     3: out_bf16 = exp(acc*alpha - c2[n] - rowvec[m])    (u)
//     4: loss[m] += mean_n (acc*rowvec[m] - images[m,n])^2
template <int EPI>
__global__ void __launch_bounds__(256)
mma_gemm(const __nv_bfloat16* __restrict__ A, const __nv_bfloat16* __restrict__ Bm,
         int Kin, int lda, int ldb, int ldc, float alpha,
         float* __restrict__ out_f32, __nv_bfloat16* __restrict__ out_bf16,
         const __nv_bfloat16* __restrict__ pik,
         const float* __restrict__ c2vec, const float* __restrict__ rowvec,
         const float* __restrict__ images, float* __restrict__ lossout)
{
    extern __shared__ char smem[];
    const uint32_t sb = s2u(smem);          // [0,32KB) A bufs, [32KB,64KB) B bufs
    const int tid = threadIdx.x, wid = tid >> 5, lane = tid & 31;
    const int m0 = blockIdx.y * 128, n0 = blockIdx.x * 128;
    const int wm = (wid & 3) * 32, wn = (wid >> 2) * 64;

    float acc[2][8][4];
#pragma unroll
    for (int i = 0; i < 2; i++)
#pragma unroll
        for (int j = 0; j < 8; j++)
#pragma unroll
            for (int q = 0; q < 4; q++) acc[i][j][q] = 0.f;

    auto loadA = [&](int c, int buf) {
#pragma unroll
        for (int u = 0; u < 4; u++) {
            int unit = tid + u * 256;                      // 0..1023
            int row = unit >> 3, seg = unit & 7;
            cp16(sb + buf * 16384 + SWZ((uint32_t)(row * 128 + seg * 16)),
                 (const char*)(A + (size_t)(m0 + row) * lda + c * 64) + seg * 16);
        }
    };
    auto loadB = [&](int c, int buf) {
#pragma unroll
        for (int u = 0; u < 4; u++) {
            int unit = tid + u * 256;
            int row = unit >> 3, seg = unit & 7;
            cp16(sb + 32768 + buf * 16384 + SWZ((uint32_t)(row * 128 + seg * 16)),
                 (const char*)(Bm + (size_t)(n0 + row) * ldb + c * 64) + seg * 16);
        }
    };

    const int nch = Kin >> 6;
    loadA(0, 0); loadB(0, 0); CP_COMMIT();

    const int lr = lane & 15, lc = (lane >> 4) * 16;       // ldmatrix row / k-halve byte

    for (int c = 0; c < nch; c++) {
        const int buf = c & 1;
        if (c + 1 < nch) {
            loadA(c + 1, buf ^ 1); loadB(c + 1, buf ^ 1); CP_COMMIT();
            CP_WAIT(1);
        } else {
            CP_WAIT(0);
        }
        __syncthreads();

        const uint32_t sA = sb + buf * 16384;
        const uint32_t sB = sb + 32768 + buf * 16384;
#pragma unroll
        for (int kk = 0; kk < 4; kk++) {
            const int kb = kk * 32 + lc;
            uint32_t a[2][4], b[4][4];
#pragma unroll
            for (int mi = 0; mi < 2; mi++)
                LDSM4(a[mi], sA + SWZ((uint32_t)((wm + mi * 16 + lr) * 128 + kb)));
#pragma unroll
            for (int pi = 0; pi < 4; pi++)
                LDSM4(b[pi], sB + SWZ((uint32_t)((wn + pi * 16 + lr) * 128 + kb)));
#pragma unroll
            for (int mi = 0; mi < 2; mi++)
#pragma unroll
                for (int ni = 0; ni < 8; ni++) {
                    const int pi = ni >> 1, sel = ni & 1;
                    MMA(acc[mi][ni], a[mi], b[pi][sel], b[pi][sel + 2]);
                }
        }
        __syncthreads();   // protect buf from next prefetch overwrite
    }

    // ---- epilogue ----
    const int g = lane >> 2, cq = lane & 3;
#pragma unroll
    for (int mi = 0; mi < 2; mi++) {
        const int r0 = m0 + wm + mi * 16 + g;
        const int r1 = r0 + 8;
        float rv0 = 1.f, rv1 = 1.f;
        if (EPI == 1) { rv0 = rowvec ? rowvec[r0] : 1.f; rv1 = rowvec ? rowvec[r1] : 1.f; }
        if (EPI == 3 || EPI == 4) { rv0 = rowvec[r0]; rv1 = rowvec[r1]; }
        float ls0 = 0.f, ls1 = 0.f;
#pragma unroll
        for (int ni = 0; ni < 8; ni++) {
            const int col = n0 + wn + ni * 8 + cq * 2;
            float v00 = acc[mi][ni][0], v01 = acc[mi][ni][1];
            float v10 = acc[mi][ni][2], v11 = acc[mi][ni][3];
            size_t i0 = (size_t)r0 * ldc + col, i1 = (size_t)r1 * ldc + col;
            if (EPI == 0) {
                float c0 = c2vec[col], c1 = c2vec[col + 1];
                *(float2*)(out_f32 + i0) = make_float2(v00 * alpha - c0, v01 * alpha - c1);
                *(float2*)(out_f32 + i1) = make_float2(v10 * alpha - c0, v11 * alpha - c1);
            } else if (EPI == 1) {
                *(__nv_bfloat162*)(out_bf16 + i0) =
                    __floats2bfloat162_rn(v00 * rv0, v01 * rv0);
                *(__nv_bfloat162*)(out_bf16 + i1) =
                    __floats2bfloat162_rn(v10 * rv1, v11 * rv1);
            } else if (EPI == 2) {
                float c0 = c2vec[col], c1 = c2vec[col + 1];
                __nv_bfloat162 p0 = *(const __nv_bfloat162*)(pik + i0);
                __nv_bfloat162 p1 = *(const __nv_bfloat162*)(pik + i1);
                *(__nv_bfloat162*)(out_bf16 + i0) = __floats2bfloat162_rn(
                    __bfloat162float(p0.x) * expf(v00 * alpha - c0),
                    __bfloat162float(p0.y) * expf(v01 * alpha - c1));
                *(__nv_bfloat162*)(out_bf16 + i1) = __floats2bfloat162_rn(
                    __bfloat162float(p1.x) * expf(v10 * alpha - c0),
                    __bfloat162float(p1.y) * expf(v11 * alpha - c1));
            } else if (EPI == 3) {
                float c0 = c2vec[col], c1 = c2vec[col + 1];
                *(__nv_bfloat162*)(out_bf16 + i0) = __floats2bfloat162_rn(
                    expf(v00 * alpha - c0 - rv0), expf(v01 * alpha - c1 - rv0));
                *(__nv_bfloat162*)(out_bf16 + i1) = __floats2bfloat162_rn(
                    expf(v10 * alpha - c0 - rv1), expf(v11 * alpha - c1 - rv1));
            } else {
                float d;
                d = v00 * rv0 - images[i0];     ls0 += d * d;
                d = v01 * rv0 - images[i0 + 1]; ls0 += d * d;
                d = v10 * rv1 - images[i1];     ls1 += d * d;
                d = v11 * rv1 - images[i1 + 1]; ls1 += d * d;
            }
        }
        if (EPI == 4) {
            ls0 += __shfl_xor_sync(0xffffffffu, ls0, 1);
            ls0 += __shfl_xor_sync(0xffffffffu, ls0, 2);
            ls1 += __shfl_xor_sync(0xffffffffu, ls1, 1);
            ls1 += __shfl_xor_sync(0xffffffffu, ls1, 2);
            if (cq == 0) {
                atomicAdd(&lossout[r0], ls0 * (1.0f / Gd));
                atomicAdd(&lossout[r1], ls1 * (1.0f / Gd));
            }
        }
    }
}

// ---------------- small kernels ----------------
__global__ void k_cvt(const float* __restrict__ s, __nv_bfloat16* __restrict__ d, int n) {
    int i = blockIdx.x * blockDim.x + threadIdx.x;
    if (i < n) d[i] = __float2bfloat16(s[i]);
}
__global__ void k_tcvt(const float* __restrict__ s, __nv_bfloat16* __restrict__ d, int R, int C) {
    int i = blockIdx.x * blockDim.x + threadIdx.x;
    if (i >= R * C) return;
    int c = i / R, r = i % R;
    d[i] = __float2bfloat16(s[(size_t)r * C + c]);
}
__global__ void k_c2(const float* __restrict__ xa, const float* __restrict__ xb) {
    int k = blockIdx.x * blockDim.x + threadIdx.x;
    if (k >= Kd) return;
    float s = 0.f;
    for (int g = 0; g < Gd; g++) { float v = xa[(size_t)g * Kd + k]; s += v * v; }
    g_c2a[k] = s / Gd;
    float t = 0.f;
    for (int e = 0; e < Ed; e++) { float v = xb[(size_t)e * Kd + k]; t += v * v; }
    g_c2b[k] = t / Ed;
}
__global__ void k_softmax(void) {
    __shared__ float red[256];
    const int b = blockIdx.x, t = threadIdx.x;
    const float* row = g_logits + (size_t)b * Kd;
    __nv_bfloat16* orow = g_pik + (size_t)b * Kd;
    float vals[8], lmax = -1e30f;
#pragma unroll
    for (int i = 0; i < 8; i++) { vals[i] = row[t + i * 256]; lmax = fmaxf(lmax, vals[i]); }
    red[t] = lmax; __syncthreads();
    for (int s = 128; s > 0; s >>= 1) { if (t < s) red[t] = fmaxf(red[t], red[t + s]); __syncthreads(); }
    float m = red[0]; __syncthreads();
    float lsum = 0.f;
#pragma unroll
    for (int i = 0; i < 8; i++) { vals[i] = expf(vals[i] - m); lsum += vals[i]; }
    red[t] = lsum; __syncthreads();
    for (int s = 128; s > 0; s >>= 1) { if (t < s) red[t] += red[t + s]; __syncthreads(); }
    float inv = 1.0f / red[0];
#pragma unroll
    for (int i = 0; i < 8; i++) orow[t + i * 256] = __float2bfloat16(vals[i] * inv);
}
__global__ void k_rowsum(const __nv_bfloat16* __restrict__ w, int mode) {
    __shared__ float red[256];
    const int b = blockIdx.x, t = threadIdx.x;
    const __nv_bfloat16* row = w + (size_t)b * Kd;
    float s = 0.f;
#pragma unroll
    for (int i = 0; i < 8; i++) s += __bfloat162float(row[t + i * 256]);
    red[t] = s; __syncthreads();
    for (int st = 128; st > 0; st >>= 1) { if (t < st) red[t] += red[t + st]; __syncthreads(); }
    if (t == 0) g_rows[b] = (mode == 0) ? 1.0f / red[0] : 1.0f / (PNULL + red[0]);
}
__global__ void k_z2(void) {
    __shared__ float red[256];
    const int b = blockIdx.x, t = threadIdx.x;
    float v = __bfloat162float(g_z[(size_t)b * Ed + t]);
    red[t] = v * v; __syncthreads();
    for (int st = 128; st > 0; st >>= 1) { if (t < st) red[t] += red[t + st]; __syncthreads(); }
    if (t == 0) g_z2[b] = red[0] / Ed;
}

// ---------------- host ----------------
extern "C" void kernel_launch(void* const* d_in, const int* in_sizes, int n_in,
                              void* d_out, int out_size) {
    (void)in_sizes; (void)n_in; (void)out_size;
    const float* images = (const float*)d_in[0];
    const float* xa     = (const float*)d_in[1];
    const float* xb     = (const float*)d_in[2];
    float* loss = (float*)d_out;

    float *logits, *c2a, *c2b, *rows, *z2;
    __nv_bfloat16 *pik, *wb, *zb, *imgs, *xab, *xaT, *xbb, *xbT;
    cudaGetSymbolAddress((void**)&logits, g_logits);
    cudaGetSymbolAddress((void**)&pik,  g_pik);
    cudaGetSymbolAddress((void**)&wb,   g_w);
    cudaGetSymbolAddress((void**)&zb,   g_z);
    cudaGetSymbolAddress((void**)&imgs, g_imgs);
    cudaGetSymbolAddress((void**)&xab,  g_xa);
    cudaGetSymbolAddress((void**)&xaT,  g_xaT);
    cudaGetSymbolAddress((void**)&xbb,  g_xb);
    cudaGetSymbolAddress((void**)&xbT,  g_xbT);
    cudaGetSymbolAddress((void**)&c2a,  g_c2a);
    cudaGetSymbolAddress((void**)&c2b,  g_c2b);
    cudaGetSymbolAddress((void**)&rows, g_rows);
    cudaGetSymbolAddress((void**)&z2,   g_z2);

    const int SMEM = 65536;
    cudaFuncSetAttribute(mma_gemm<0>, cudaFuncAttributeMaxDynamicSharedMemorySize, SMEM);
    cudaFuncSetAttribute(mma_gemm<1>, cudaFuncAttributeMaxDynamicSharedMemorySize, SMEM);
    cudaFuncSetAttribute(mma_gemm<2>, cudaFuncAttributeMaxDynamicSharedMemorySize, SMEM);
    cudaFuncSetAttribute(mma_gemm<3>, cudaFuncAttributeMaxDynamicSharedMemorySize, SMEM);
    cudaFuncSetAttribute(mma_gemm<4>, cudaFuncAttributeMaxDynamicSharedMemorySize, SMEM);

    dim3 blk(256);
    // one-time conversions
    k_cvt<<<(Bsz * Gd + 255) / 256, blk>>>(images, imgs, Bsz * Gd);
    k_cvt<<<(Gd * Kd + 255) / 256, blk>>>(xa, xab, Gd * Kd);
    k_cvt<<<(Ed * Kd + 255) / 256, blk>>>(xb, xbb, Ed * Kd);
    k_tcvt<<<(Gd * Kd + 255) / 256, blk>>>(xa, xaT, Gd, Kd);  // (K,G)
    k_tcvt<<<(Ed * Kd + 255) / 256, blk>>>(xb, xbT, Ed, Kd);  // (K,E)
    k_c2<<<Kd / 256, blk>>>(xa, xb);

    dim3 gK(Kd / 128, Bsz / 128);   // (16,64)
    dim3 gE(Ed / 128, Bsz / 128);   // (2,64)
    dim3 gG(Gd / 128, Bsz / 128);   // (8,64)

    // logits = images@xa * 2/G - c2a  -> fp32
    mma_gemm<0><<<gK, 256, SMEM>>>(imgs, xaT, Gd, Gd, Gd, Kd, 2.0f / Gd,
                                   logits, nullptr, nullptr, c2a, nullptr, nullptr, nullptr);
    k_softmax<<<Bsz, blk>>>();  // -> bf16 pik

    // z = pik @ xb^T
    mma_gemm<1><<<gE, 256, SMEM>>>(pik, xbb, Kd, Kd, Kd, Ed, 1.0f,
                                   nullptr, zb, nullptr, nullptr, nullptr, nullptr, nullptr);
    for (int s = 0; s < 4; s++) {
        // w = pik * exp((z@xb)*2/E - c2b)
        mma_gemm<2><<<gK, 256, SMEM>>>(zb, xbT, Ed, Ed, Ed, Kd, 2.0f / Ed,
                                       nullptr, wb, pik, c2b, nullptr, nullptr, nullptr);
        k_rowsum<<<Bsz, blk>>>(wb, 0);
        // z = (w @ xb^T) / sum(w)
        mma_gemm<1><<<gE, 256, SMEM>>>(wb, xbb, Kd, Kd, Kd, Ed, 1.0f,
                                       nullptr, zb, nullptr, nullptr, rows, nullptr, nullptr);
    }
    // decode
    k_z2<<<Bsz, blk>>>();
    mma_gemm<3><<<gK, 256, SMEM>>>(zb, xbT, Ed, Ed, Ed, Kd, 2.0f / Ed,
                                   nullptr, wb, nullptr, c2b, z2, nullptr, nullptr);
    k_rowsum<<<Bsz, blk>>>(wb, 1);
    cudaMemsetAsync(loss, 0, Bsz * sizeof(float));
    // loss[b] = mean_g ((u/denom)@xa^T - images)^2
    mma_gemm<4><<<gG, 256, SMEM>>>(wb, xab, Kd, Kd, Kd, Gd, 1.0f,
                                   nullptr, nullptr, nullptr, nullptr, rows, images, loss);
}

// round 4
// speedup vs baseline: 7.1080x; 1.0974x over previous
#include <cuda_runtime.h>
#include <cuda_bf16.h>
#include <math.h>
#include <stdint.h>

#define Bsz 8192
#define Gd  1024
#define Ed  256
#define Kd  2048
#define PNULL 0.1f

// ---------------- scratch (device globals; no allocs allowed) ----------------
__device__ __nv_bfloat16  g_pik  [(size_t)Bsz * Kd];    // 32 MB (unnormalized exp)
__device__ __nv_bfloat16  g_w    [(size_t)Bsz * Kd];    // 32 MB: w / u scratch
__device__ __nv_bfloat16  g_z    [(size_t)Bsz * Ed];    // 4 MB
__device__ __nv_bfloat16  g_imgs [(size_t)Bsz * Gd];    // 16 MB
__device__ __nv_bfloat16  g_xa   [(size_t)Gd * Kd];     // (G,K)
__device__ __nv_bfloat16  g_xaT  [(size_t)Kd * Gd];     // (K,G)
__device__ __nv_bfloat16  g_xb   [(size_t)Ed * Kd];     // (E,K)
__device__ __nv_bfloat16  g_xbT  [(size_t)Kd * Ed];     // (K,E)
__device__ float g_c2a[Kd], g_c2b[Kd], g_sums[Bsz], g_z2[Bsz];

// ---------------- helpers ----------------
__device__ __forceinline__ uint32_t s2u(const void* p) {
    uint32_t a;
    asm("{ .reg .u64 t; cvta.to.shared.u64 t, %1; cvt.u32.u64 %0, t; }" : "=r"(a) : "l"(p));
    return a;
}
#define SWZ(o) ((o) ^ (((o) >> 3) & 0x70))

__device__ __forceinline__ void cp16(uint32_t dst, const void* src) {
    asm volatile("cp.async.cg.shared.global [%0], [%1], 16;" :: "r"(dst), "l"(src));
}
#define CP_COMMIT()   asm volatile("cp.async.commit_group;" ::: "memory")
#define CP_WAIT(n)    asm volatile("cp.async.wait_group %0;" :: "n"(n) : "memory")

#define LDSM4(r, addr)                                                              \
    asm volatile("ldmatrix.sync.aligned.m8n8.x4.shared.b16 {%0,%1,%2,%3}, [%4];"    \
        : "=r"((r)[0]), "=r"((r)[1]), "=r"((r)[2]), "=r"((r)[3]) : "r"(addr))

#define MMA(d, a, b0, b1)                                                           \
    asm volatile("mma.sync.aligned.m16n8k16.row.col.f32.bf16.bf16.f32 "             \
        "{%0,%1,%2,%3}, {%4,%5,%6,%7}, {%8,%9}, {%0,%1,%2,%3};"                     \
        : "+f"((d)[0]), "+f"((d)[1]), "+f"((d)[2]), "+f"((d)[3])                    \
        : "r"((a)[0]), "r"((a)[1]), "r"((a)[2]), "r"((a)[3]), "r"(b0), "r"(b1))

// ---------------- mma.sync GEMM: D[128 x 128] tile = A(MxK,K-major) . B(NxK,K-major)^T
// EPI 0: e = exp(acc*alpha - c2[n]); out=e (bf16); redout[m] += sum_n e   (pik gen)
//     1: out = acc / rowvec[m]                                            (z)
//     2: w = pik[m,n]*exp(acc*alpha - c2[n]); out=w; redout[m] += sum w   (w)
//     3: u = exp(acc*alpha - c2[n] - rowvec[m]); out=u; redout[m] += sum  (u, rowvec=z2)
//     4: d = acc/(PNULL+rowvec[m]) - images[m,n]; redout[m] += d^2/G      (loss)
//     5: t = acc / rowvec[m]; out=t; redout[m] += t^2/E                   (z + z2)
template <int EPI>
__global__ void __launch_bounds__(256, 2)
mma_gemm(const __nv_bfloat16* __restrict__ A, const __nv_bfloat16* __restrict__ Bm,
         int Kin, int lda, int ldb, int ldc, float alpha,
         __nv_bfloat16* __restrict__ out_bf16,
         const __nv_bfloat16* __restrict__ pik,
         const float* __restrict__ c2vec, const float* __restrict__ rowvec,
         const float* __restrict__ images, float* __restrict__ redout)
{
    extern __shared__ char smem[];
    const uint32_t sb = s2u(smem);      // A stages: 0,16K,32K ; B stages: 48K,64K,80K
    const int tid = threadIdx.x, wid = tid >> 5, lane = tid & 31;
    const int m0 = blockIdx.y * 128, n0 = blockIdx.x * 128;
    const int wm = (wid & 3) * 32, wn = (wid >> 2) * 64;

    float acc[2][8][4];
#pragma unroll
    for (int i = 0; i < 2; i++)
#pragma unroll
        for (int j = 0; j < 8; j++)
#pragma unroll
            for (int q = 0; q < 4; q++) acc[i][j][q] = 0.f;

    auto loadA = [&](int c, int st) {
#pragma unroll
        for (int u = 0; u < 4; u++) {
            int unit = tid + u * 256;                      // 0..1023
            int row = unit >> 3, seg = unit & 7;
            cp16(sb + st * 16384 + SWZ((uint32_t)(row * 128 + seg * 16)),
                 (const char*)(A + (size_t)(m0 + row) * lda + c * 64) + seg * 16);
        }
    };
    auto loadB = [&](int c, int st) {
#pragma unroll
        for (int u = 0; u < 4; u++) {
            int unit = tid + u * 256;
            int row = unit >> 3, seg = unit & 7;
            cp16(sb + 49152 + st * 16384 + SWZ((uint32_t)(row * 128 + seg * 16)),
                 (const char*)(Bm + (size_t)(n0 + row) * ldb + c * 64) + seg * 16);
        }
    };

    const int nch = Kin >> 6;
    loadA(0, 0); loadB(0, 0); CP_COMMIT();
    if (nch > 1) { loadA(1, 1); loadB(1, 1); CP_COMMIT(); }

    const int lr = lane & 15, lc = (lane >> 4) * 16;

    for (int c = 0; c < nch; c++) {
        if (c == nch - 1) { CP_WAIT(0); } else { CP_WAIT(1); }
        __syncthreads();                       // stage c visible to all; prior compute done
        if (c + 2 < nch) {                     // prefetch AFTER barrier: no overwrite race
            loadA(c + 2, (c + 2) % 3); loadB(c + 2, (c + 2) % 3); CP_COMMIT();
        }
        const int st = c % 3;
        const uint32_t sA = sb + st * 16384;
        const uint32_t sB = sb + 49152 + st * 16384;
#pragma unroll
        for (int kk = 0; kk < 4; kk++) {
            const int kb = kk * 32 + lc;
            uint32_t a[2][4], b[4][4];
#pragma unroll
            for (int mi = 0; mi < 2; mi++)
                LDSM4(a[mi], sA + SWZ((uint32_t)((wm + mi * 16 + lr) * 128 + kb)));
#pragma unroll
            for (int pi = 0; pi < 4; pi++)
                LDSM4(b[pi], sB + SWZ((uint32_t)((wn + pi * 16 + lr) * 128 + kb)));
#pragma unroll
            for (int mi = 0; mi < 2; mi++)
#pragma unroll
                for (int ni = 0; ni < 8; ni++) {
                    const int pi = ni >> 1, sel = ni & 1;
                    MMA(acc[mi][ni], a[mi], b[pi][sel], b[pi][sel + 2]);
                }
        }
    }

    // ---- epilogue ----
    const int g = lane >> 2, cq = lane & 3;
    constexpr float rscale = (EPI == 4) ? 1.0f / Gd : (EPI == 5) ? 1.0f / Ed : 1.0f;
#pragma unroll
    for (int mi = 0; mi < 2; mi++) {
        const int r0 = m0 + wm + mi * 16 + g;
        const int r1 = r0 + 8;
        float rv0 = 1.f, rv1 = 1.f;
        if (EPI == 1 || EPI == 5) { rv0 = 1.0f / rowvec[r0]; rv1 = 1.0f / rowvec[r1]; }
        if (EPI == 3) { rv0 = rowvec[r0]; rv1 = rowvec[r1]; }
        if (EPI == 4) { rv0 = 1.0f / (PNULL + rowvec[r0]); rv1 = 1.0f / (PNULL + rowvec[r1]); }
        float ls0 = 0.f, ls1 = 0.f;
#pragma unroll
        for (int ni = 0; ni < 8; ni++) {
            const int col = n0 + wn + ni * 8 + cq * 2;
            float v00 = acc[mi][ni][0], v01 = acc[mi][ni][1];
            float v10 = acc[mi][ni][2], v11 = acc[mi][ni][3];
            size_t i0 = (size_t)r0 * ldc + col, i1 = (size_t)r1 * ldc + col;
            if (EPI == 0) {
                float c0 = c2vec[col], c1 = c2vec[col + 1];
                float e00 = expf(v00 * alpha - c0), e01 = expf(v01 * alpha - c1);
                float e10 = expf(v10 * alpha - c0), e11 = expf(v11 * alpha - c1);
                *(__nv_bfloat162*)(out_bf16 + i0) = __floats2bfloat162_rn(e00, e01);
                *(__nv_bfloat162*)(out_bf16 + i1) = __floats2bfloat162_rn(e10, e11);
                ls0 += e00 + e01; ls1 += e10 + e11;
            } else if (EPI == 1) {
                *(__nv_bfloat162*)(out_bf16 + i0) = __floats2bfloat162_rn(v00 * rv0, v01 * rv0);
                *(__nv_bfloat162*)(out_bf16 + i1) = __floats2bfloat162_rn(v10 * rv1, v11 * rv1);
            } else if (EPI == 5) {
                float t00 = v00 * rv0, t01 = v01 * rv0;
                float t10 = v10 * rv1, t11 = v11 * rv1;
                *(__nv_bfloat162*)(out_bf16 + i0) = __floats2bfloat162_rn(t00, t01);
                *(__nv_bfloat162*)(out_bf16 + i1) = __floats2bfloat162_rn(t10, t11);
                ls0 += t00 * t00 + t01 * t01; ls1 += t10 * t10 + t11 * t11;
            } else if (EPI == 2) {
                float c0 = c2vec[col], c1 = c2vec[col + 1];
                __nv_bfloat162 p0 = *(const __nv_bfloat162*)(pik + i0);
                __nv_bfloat162 p1 = *(const __nv_bfloat162*)(pik + i1);
                float w00 = __bfloat162float(p0.x) * expf(v00 * alpha - c0);
                float w01 = __bfloat162float(p0.y) * expf(v01 * alpha - c1);
                float w10 = __bfloat162float(p1.x) * expf(v10 * alpha - c0);
                float w11 = __bfloat162float(p1.y) * expf(v11 * alpha - c1);
                *(__nv_bfloat162*)(out_bf16 + i0) = __floats2bfloat162_rn(w00, w01);
                *(__nv_bfloat162*)(out_bf16 + i1) = __floats2bfloat162_rn(w10, w11);
                ls0 += w00 + w01; ls1 += w10 + w11;
            } else if (EPI == 3) {
                float c0 = c2vec[col], c1 = c2vec[col + 1];
                float u00 = expf(v00 * alpha - c0 - rv0), u01 = expf(v01 * alpha - c1 - rv0);
                float u10 = expf(v10 * alpha - c0 - rv1), u11 = expf(v11 * alpha - c1 - rv1);
                *(__nv_bfloat162*)(out_bf16 + i0) = __floats2bfloat162_rn(u00, u01);
                *(__nv_bfloat162*)(out_bf16 + i1) = __floats2bfloat162_rn(u10, u11);
                ls0 += u00 + u01; ls1 += u10 + u11;
            } else {  // EPI 4
                float d;
                d = v00 * rv0 - images[i0];     ls0 += d * d;
                d = v01 * rv0 - images[i0 + 1]; ls0 += d * d;
                d = v10 * rv1 - images[i1];     ls1 += d * d;
                d = v11 * rv1 - images[i1 + 1]; ls1 += d * d;
            }
        }
        if (EPI != 1) {
            ls0 += __shfl_xor_sync(0xffffffffu, ls0, 1);
            ls0 += __shfl_xor_sync(0xffffffffu, ls0, 2);
            ls1 += __shfl_xor_sync(0xffffffffu, ls1, 1);
            ls1 += __shfl_xor_sync(0xffffffffu, ls1, 2);
            if (cq == 0) {
                atomicAdd(&redout[r0], ls0 * rscale);
                atomicAdd(&redout[r1], ls1 * rscale);
            }
        }
    }
}

// ---------------- small kernels ----------------
__global__ void k_cvt4(const float4* __restrict__ s, __nv_bfloat162* __restrict__ d, int n4) {
    int i = blockIdx.x * blockDim.x + threadIdx.x;
    if (i < n4) {
        float4 v = s[i];
        d[2 * i]     = __floats2bfloat162_rn(v.x, v.y);
        d[2 * i + 1] = __floats2bfloat162_rn(v.z, v.w);
    }
}
// tiled transpose+convert: dst (C,R) bf16 = src (R,C)^T fp32
__global__ void k_tcvtT(const float* __restrict__ s, __nv_bfloat16* __restrict__ d, int R, int C) {
    __shared__ float t[32][33];
    int c0 = blockIdx.x * 32, r0 = blockIdx.y * 32;
    int tx = threadIdx.x, ty = threadIdx.y;       // block (32,8)
#pragma unroll
    for (int j = 0; j < 32; j += 8) t[ty + j][tx] = s[(size_t)(r0 + ty + j) * C + c0 + tx];
    __syncthreads();
#pragma unroll
    for (int j = 0; j < 32; j += 8)
        d[(size_t)(c0 + ty + j) * R + r0 + tx] = __float2bfloat16(t[tx][ty + j]);
}
__global__ void k_c2(const float* __restrict__ xa, const float* __restrict__ xb) {
    int k = blockIdx.x * blockDim.x + threadIdx.x;
    if (k >= Kd) return;
    float s = 0.f;
    for (int g = 0; g < Gd; g++) { float v = xa[(size_t)g * Kd + k]; s += v * v; }
    g_c2a[k] = s / Gd;
    float t = 0.f;
    for (int e = 0; e < Ed; e++) { float v = xb[(size_t)e * Kd + k]; t += v * v; }
    g_c2b[k] = t / Ed;
}

// ---------------- host ----------------
extern "C" void kernel_launch(void* const* d_in, const int* in_sizes, int n_in,
                              void* d_out, int out_size) {
    (void)in_sizes; (void)n_in; (void)out_size;
    const float* images = (const float*)d_in[0];
    const float* xa     = (const float*)d_in[1];
    const float* xb     = (const float*)d_in[2];
    float* loss = (float*)d_out;

    float *c2a, *c2b, *sums, *z2;
    __nv_bfloat16 *pik, *wb, *zb, *imgs, *xab, *xaT, *xbb, *xbT;
    cudaGetSymbolAddress((void**)&pik,  g_pik);
    cudaGetSymbolAddress((void**)&wb,   g_w);
    cudaGetSymbolAddress((void**)&zb,   g_z);
    cudaGetSymbolAddress((void**)&imgs, g_imgs);
    cudaGetSymbolAddress((void**)&xab,  g_xa);
    cudaGetSymbolAddress((void**)&xaT,  g_xaT);
    cudaGetSymbolAddress((void**)&xbb,  g_xb);
    cudaGetSymbolAddress((void**)&xbT,  g_xbT);
    cudaGetSymbolAddress((void**)&c2a,  g_c2a);
    cudaGetSymbolAddress((void**)&c2b,  g_c2b);
    cudaGetSymbolAddress((void**)&sums, g_sums);
    cudaGetSymbolAddress((void**)&z2,   g_z2);

    const int SMEM = 98304;
    cudaFuncSetAttribute(mma_gemm<0>, cudaFuncAttributeMaxDynamicSharedMemorySize, SMEM);
    cudaFuncSetAttribute(mma_gemm<1>, cudaFuncAttributeMaxDynamicSharedMemorySize, SMEM);
    cudaFuncSetAttribute(mma_gemm<2>, cudaFuncAttributeMaxDynamicSharedMemorySize, SMEM);
    cudaFuncSetAttribute(mma_gemm<3>, cudaFuncAttributeMaxDynamicSharedMemorySize, SMEM);
    cudaFuncSetAttribute(mma_gemm<4>, cudaFuncAttributeMaxDynamicSharedMemorySize, SMEM);
    cudaFuncSetAttribute(mma_gemm<5>, cudaFuncAttributeMaxDynamicSharedMemorySize, SMEM);

    // one-time conversions
    k_cvt4<<<(Bsz * Gd / 4 + 255) / 256, 256>>>((const float4*)images, (__nv_bfloat162*)imgs, Bsz * Gd / 4);
    k_cvt4<<<(Gd * Kd / 4 + 255) / 256, 256>>>((const float4*)xa, (__nv_bfloat162*)xab, Gd * Kd / 4);
    k_cvt4<<<(Ed * Kd / 4 + 255) / 256, 256>>>((const float4*)xb, (__nv_bfloat162*)xbb, Ed * Kd / 4);
    k_tcvtT<<<dim3(Kd / 32, Gd / 32), dim3(32, 8)>>>(xa, xaT, Gd, Kd);  // (K,G)
    k_tcvtT<<<dim3(Kd / 32, Ed / 32), dim3(32, 8)>>>(xb, xbT, Ed, Kd);  // (K,E)
    k_c2<<<Kd / 256, 256>>>(xa, xb);

    dim3 gK(Kd / 128, Bsz / 128);   // (16,64)
    dim3 gE(Ed / 128, Bsz / 128);   // (2,64)
    dim3 gG(Gd / 128, Bsz / 128);   // (8,64)

    // pik_unnorm = exp(images@xa*2/G - c2a), sums = row sums (softmax denominator)
    cudaMemsetAsync(sums, 0, Bsz * sizeof(float));
    mma_gemm<0><<<gK, 256, SMEM>>>(imgs, xaT, Gd, Gd, Gd, Kd, 2.0f / Gd,
                                   pik, nullptr, c2a, nullptr, nullptr, sums);
    // z = (pik_unnorm @ xb^T) / sums   (== softmax(pik) @ xb^T)
    mma_gemm<1><<<gE, 256, SMEM>>>(pik, xbb, Kd, Kd, Kd, Ed, 1.0f,
                                   zb, nullptr, nullptr, sums, nullptr, nullptr);
    // 4 EM steps; P_NULL and exp(-z2) row constants cancel in xp = w/sum(w)
    for (int s = 0; s < 4; s++) {
        cudaMemsetAsync(sums, 0, Bsz * sizeof(float));
        // w = pik * exp((z@xb)*2/E - c2b); sums = row sums(w)
        mma_gemm<2><<<gK, 256, SMEM>>>(zb, xbT, Ed, Ed, Ed, Kd, 2.0f / Ed,
                                       wb, pik, c2b, nullptr, nullptr, sums);
        if (s < 3) {
            mma_gemm<1><<<gE, 256, SMEM>>>(wb, xbb, Kd, Kd, Kd, Ed, 1.0f,
                                           zb, nullptr, nullptr, sums, nullptr, nullptr);
        } else {
            // last step also accumulates z2 = mean_e z^2 for decode
            cudaMemsetAsync(z2, 0, Bsz * sizeof(float));
            mma_gemm<5><<<gE, 256, SMEM>>>(wb, xbb, Kd, Kd, Kd, Ed, 1.0f,
                                           zb, nullptr, nullptr, sums, nullptr, z2);
        }
    }
    // decode: u = exp((z@xb)*2/E - c2b - z2); sums = row sums(u)
    cudaMemsetAsync(sums, 0, Bsz * sizeof(float));
    mma_gemm<3><<<gK, 256, SMEM>>>(zb, xbT, Ed, Ed, Ed, Kd, 2.0f / Ed,
                                   wb, nullptr, c2b, z2, nullptr, sums);
    // loss[b] = mean_g ((u/(0.1+sums)) @ xa^T - images)^2
    cudaMemsetAsync(loss, 0, Bsz * sizeof(float));
    mma_gemm<4><<<gG, 256, SMEM>>>(wb, xab, Kd, Kd, Kd, Gd, 1.0f,
                                   nullptr, nullptr, nullptr, sums, images, loss);
}